// round 7
// baseline (speedup 1.0000x reference)
#include <cuda_runtime.h>
#include <math.h>
#include <stddef.h>

#define H      128
#define G4     512           // 4*H
#define T_OBS  8
#define PRED   12
#define NNB    64
#define EMB    32
#define NCELL  16            // 4x4 grid cells reachable after clamp
#define KF     18            // small-feature dims: [obs/prev(2) | counts(16)]
#define KX     148           // padded x / weight row length: 128 + 18 + 2 pad
#define BT     32            // batch rows per CTA
#define THREADS_R 128
#define BMAX   16384
#define NK4    (KX/4)        // 37

// ---------------- device scratch (static: no allocations allowed) ----------------
// g_W2 layout: [chunk cc(8)][gate(4)*16 + jloc(16)][KX]  (chunk = 16 consecutive j, all 4 gates)
__device__ __align__(128) float g_W2[G4 * KX];
__device__ __align__(128) float g_bias[2 * G4];            // [0:512]=obs bias, [512:1024]=pred bias
__device__ __align__(128) float g_feat[BMAX * T_OBS * KF]; // per (b,t): [obs_x,obs_y,counts0..15]

__device__ __forceinline__ float sigf(float x) { return 1.0f / (1.0f + __expf(-x)); }

// packed f32x2 FMA: d.lo += a.lo*b.lo ; d.hi += a.hi*b.hi   (SASS: FFMA2)
__device__ __forceinline__ void ffma2(unsigned long long& d, unsigned long long a, unsigned long long b) {
    asm("fma.rn.f32x2 %0, %1, %2, %0;" : "+l"(d) : "l"(a), "l"(b));
}
__device__ __forceinline__ unsigned long long packf2(float lo, float hi) {
    return ((unsigned long long)__float_as_uint(hi) << 32) | (unsigned long long)__float_as_uint(lo);
}
__device__ __forceinline__ float pairsum(unsigned long long v) {
    return __uint_as_float((unsigned)(v & 0xffffffffu)) + __uint_as_float((unsigned)(v >> 32));
}

// ---------------- kernel 1: fold weights (one warp per gate row) ----------------
// gates[g] = sum_k h[k]*W_hh[g,k] + obs·A[g,:] + counts·D[g,:] + bias
// A = W_ih[:, :H] @ W_in ; D = (W_ih[:, H:] @ W_sp) @ embed^T ; biases folded.
__global__ void prep_kernel(const float* __restrict__ W_in, const float* __restrict__ b_in,
                            const float* __restrict__ W_sp, const float* __restrict__ b_sp,
                            const float* __restrict__ W_ih, const float* __restrict__ W_hh,
                            const float* __restrict__ b_ih, const float* __restrict__ b_hh,
                            const float* __restrict__ embed)
{
    int g    = blockIdx.x * 4 + (threadIdx.x >> 5);
    int lane = threadIdx.x & 31;
    if (g >= G4) return;
    int gate = g >> 7, j = g & 127;
    int cc = j >> 4, jloc = j & 15;
    float* row = g_W2 + (size_t)(cc * 64 + gate * 16 + jloc) * KX;
    const float* wih = W_ih + (size_t)g * 256;
    const float* whh = W_hh + (size_t)g * H;

    for (int k = lane; k < H; k += 32) row[k] = whh[k];

    // Ce = C[lane] = sum_j wih[H+j] * W_sp[j][lane]   (coalesced W_sp reads)
    float Ce = 0.f;
    #pragma unroll 4
    for (int jj = 0; jj < H; jj++)
        Ce += wih[H + jj] * W_sp[jj * EMB + lane];

    // lane-partitioned scalar sums
    float a0 = 0.f, a1 = 0.f, s1 = 0.f, s2 = 0.f;
    for (int jj = lane; jj < H; jj += 32) {
        float w1 = wih[jj], w2 = wih[H + jj];
        a0 += w1 * W_in[jj * 2 + 0];
        a1 += w1 * W_in[jj * 2 + 1];
        s1 += w1 * b_in[jj];
        s2 += w2 * b_sp[jj];
    }
    #pragma unroll
    for (int off = 16; off; off >>= 1) {
        a0 += __shfl_xor_sync(0xffffffffu, a0, off);
        a1 += __shfl_xor_sync(0xffffffffu, a1, off);
        s1 += __shfl_xor_sync(0xffffffffu, s1, off);
        s2 += __shfl_xor_sync(0xffffffffu, s2, off);
    }
    // D[c] = sum_e C[e] * embed[c][e]
    for (int c = 0; c < NCELL; c++) {
        float v = Ce * embed[c * EMB + lane];
        #pragma unroll
        for (int off = 16; off; off >>= 1) v += __shfl_xor_sync(0xffffffffu, v, off);
        if (lane == 0) row[H + 2 + c] = v;
    }
    if (lane == 0) {
        row[H + 0] = a0; row[H + 1] = a1;
        row[146] = 0.f;  row[147] = 0.f;
        float bb = b_ih[g] + b_hh[g] + s1;
        g_bias[g]      = bb + s2;   // obs steps (social bias present)
        g_bias[G4 + g] = bb;        // pred steps (social half exactly zero)
    }
}

// ---------------- kernel 2: neighbor histogram -> feat (unchanged, passes) ----------------
__global__ void hist_kernel(const float* __restrict__ obs, const float* __restrict__ nbr, int B)
{
    __shared__ int cnt[4][T_OBS][NCELL];
    int w = threadIdx.x >> 5, lane = threadIdx.x & 31;
    int b = blockIdx.x * 4 + w;

    for (int i = threadIdx.x; i < 4 * T_OBS * NCELL; i += blockDim.x)
        ((int*)cnt)[i] = 0;
    __syncthreads();

    if (b < B) {
        float of[16];
        const float4* op = (const float4*)(obs + (size_t)b * T_OBS * 2);
        #pragma unroll
        for (int q = 0; q < 4; q++) {
            float4 v = op[q];
            of[4 * q + 0] = v.x; of[4 * q + 1] = v.y; of[4 * q + 2] = v.z; of[4 * q + 3] = v.w;
        }
        #pragma unroll
        for (int half = 0; half < 2; half++) {
            int nn = lane + half * 32;
            const float4* np = (const float4*)(nbr + ((size_t)b * NNB + nn) * T_OBS * 2);
            float nf[16];
            #pragma unroll
            for (int q = 0; q < 4; q++) {
                float4 v = np[q];
                nf[4 * q + 0] = v.x; nf[4 * q + 1] = v.y; nf[4 * q + 2] = v.z; nf[4 * q + 3] = v.w;
            }
            #pragma unroll
            for (int t = 0; t < T_OBS; t++) {
                float rx = nf[2 * t + 0] - of[2 * t + 0];
                float ry = nf[2 * t + 1] - of[2 * t + 1];
                int ix = (int)floorf(rx * 2.0f);
                int iy = (int)floorf(ry * 2.0f);
                ix = max(-2, min(1, ix)) + 2;
                iy = max(-2, min(1, iy)) + 2;
                atomicAdd(&cnt[w][t][ix * 4 + iy], 1);
            }
        }
    }
    __syncthreads();

    if (b < B) {
        for (int i = lane; i < T_OBS * KF; i += 32) {
            int t = i / KF, c = i % KF;
            float v = (c < 2) ? obs[((size_t)b * T_OBS + t) * 2 + c]
                              : (float)cnt[w][t][c - 2];
            g_feat[((size_t)b * T_OBS + t) * KF + c] = v;
        }
    }
}

// ---------------- kernel 3: fused recurrent LSTM (FFMA2 inner loop) ----------------
// Threads: lane = batch row b (32), warp = jq (4). Each thread owns one b-row and
// 128 gate outputs (8 chunks x 4 j x 4 gates); c-state in 32 registers.
// Per chunk: 64 weight rows [gate*16 + jloc] staged to smem; weight LDS are
// warp-broadcast (all lanes same address); x LDS are conflict-free (stride 148).
__global__ void __launch_bounds__(THREADS_R)
lstm_kernel(const float* __restrict__ W_out, const float* __restrict__ b_out,
            float* __restrict__ out, int B)
{
    extern __shared__ float sm[];
    float* sh_x    = sm;                      // BT*KX   = 4736
    float* sh_w    = sh_x + BT * KX;          // 64*KX   = 9472 (one chunk)
    float* sh_h    = sh_w + 64 * KX;          // BT*129  = 4128 (stride-129: conflict-free)
    float* sh_bias = sh_h + BT * 129;         // 1024
    float* sh_wout = sh_bias + 2 * G4;        // 258

    const int tid  = threadIdx.x;
    const int b    = tid & 31;                // lane = batch row
    const int jq   = tid >> 5;                // warp = j-quarter
    const int gb0  = blockIdx.x * BT;

    for (int i = tid; i < BT * KX; i += THREADS_R) sh_x[i] = 0.f;
    for (int i = tid; i < 2 * G4; i += THREADS_R) sh_bias[i] = g_bias[i];
    for (int i = tid; i < 2 * H; i += THREADS_R) sh_wout[i] = W_out[i];
    if (tid == 0) { sh_wout[2 * H] = b_out[0]; sh_wout[2 * H + 1] = b_out[1]; }

    float cst[8][4];                          // c-state: j = cc*16 + jq*4 + jl
    #pragma unroll
    for (int cc = 0; cc < 8; cc++)
        #pragma unroll
        for (int jl = 0; jl < 4; jl++) cst[cc][jl] = 0.f;

    __syncthreads();

    const float* xrow = sh_x + b * KX;
    const float* wquarter = sh_w + (jq << 2) * KX;   // + (gt*16 + jl)*KX via immediates

    for (int step = 0; step < T_OBS + PRED; step++) {
        const bool isObs = (step < T_OBS);

        if (isObs) {
            for (int i = tid; i < BT * KF; i += THREADS_R) {
                int bb = i / KF, c = i % KF;
                sh_x[bb * KX + H + c] = g_feat[((size_t)(gb0 + bb) * T_OBS + step) * KF + c];
            }
        } else if (step == T_OBS) {
            for (int i = tid; i < BT * KF; i += THREADS_R) {
                int bb = i / KF, c = i % KF;
                sh_x[bb * KX + H + c] = 0.f;   // prev0 = 0, no counts in pred
            }
        }
        const float* bias = sh_bias + (isObs ? 0 : G4);
        __syncthreads();

        #pragma unroll 1
        for (int cc = 0; cc < 8; cc++) {
            // stage 64 weight rows (contiguous in g_W2 thanks to prep's permute)
            {
                const float4* s4 = (const float4*)(g_W2 + (size_t)cc * 64 * KX);
                float4* d4 = (float4*)sh_w;
                for (int q = tid; q < 64 * NK4; q += THREADS_R) d4[q] = s4[q];
            }
            __syncthreads();

            unsigned long long acc[4][4];      // [jl][gate] as (even-k, odd-k) partials
            #pragma unroll
            for (int jl = 0; jl < 4; jl++)
                #pragma unroll
                for (int gt = 0; gt < 4; gt++)
                    acc[jl][gt] = packf2(bias[gt * H + cc * 16 + (jq << 2) + jl], 0.f);

            #pragma unroll 2
            for (int k4 = 0; k4 < NK4; k4++) {
                ulonglong2 xv = *(const ulonglong2*)(xrow + (k4 << 2));
                #pragma unroll
                for (int gt = 0; gt < 4; gt++)
                    #pragma unroll
                    for (int jl = 0; jl < 4; jl++) {
                        ulonglong2 wv = *(const ulonglong2*)(wquarter + (gt * 16 + jl) * KX + (k4 << 2));
                        ffma2(acc[jl][gt], xv.x, wv.x);
                        ffma2(acc[jl][gt], xv.y, wv.y);
                    }
            }

            #pragma unroll
            for (int jl = 0; jl < 4; jl++) {
                float gi = pairsum(acc[jl][0]);
                float gf = pairsum(acc[jl][1]);
                float gg = pairsum(acc[jl][2]);
                float go = pairsum(acc[jl][3]);
                float c = cst[cc][jl];
                c = sigf(gf) * c + sigf(gi) * tanhf(gg);
                cst[cc][jl] = c;
                sh_h[b * 129 + cc * 16 + (jq << 2) + jl] = sigf(go) * tanhf(c);
            }
            __syncthreads();   // sh_w reads + sh_h writes complete
        }

        // commit new h into x buffer
        for (int i = tid; i < BT * H; i += THREADS_R) {
            int bb = i >> 7, j = i & 127;
            sh_x[bb * KX + j] = sh_h[bb * 129 + j];
        }
        __syncthreads();

        // prediction epilogue: disp = h @ W_out^T + b_out ; feed back as prev
        if (!isObs) {
            if (tid < BT) {
                float d0 = sh_wout[2 * H], d1 = sh_wout[2 * H + 1];
                const float* hr = sh_x + tid * KX;
                #pragma unroll 8
                for (int k = 0; k < H; k++) {
                    float hv = hr[k];
                    d0 += hv * sh_wout[k];
                    d1 += hv * sh_wout[H + k];
                }
                int p = step - T_OBS;
                size_t ob = ((size_t)(gb0 + tid) * PRED + p) * 2;
                out[ob]     = d0;
                out[ob + 1] = d1;
                sh_x[tid * KX + H]     = d0;
                sh_x[tid * KX + H + 1] = d1;
            }
            __syncthreads();
        }
    }
}

// ---------------- launch ----------------
extern "C" void kernel_launch(void* const* d_in, const int* in_sizes, int n_in,
                              void* d_out, int out_size)
{
    const float* obs   = (const float*)d_in[0];
    const float* nbr   = (const float*)d_in[1];
    const float* embed = (const float*)d_in[2];
    const float* W_in  = (const float*)d_in[3];
    const float* b_in  = (const float*)d_in[4];
    const float* W_sp  = (const float*)d_in[5];
    const float* b_sp  = (const float*)d_in[6];
    const float* W_ih  = (const float*)d_in[7];
    const float* W_hh  = (const float*)d_in[8];
    const float* b_ih  = (const float*)d_in[9];
    const float* b_hh  = (const float*)d_in[10];
    const float* W_out = (const float*)d_in[11];
    const float* b_out = (const float*)d_in[12];
    float* out = (float*)d_out;

    int B = in_sizes[0] / (T_OBS * 2);

    prep_kernel<<<G4 / 4, 128>>>(W_in, b_in, W_sp, b_sp, W_ih, W_hh, b_ih, b_hh, embed);
    hist_kernel<<<(B + 3) / 4, 128>>>(obs, nbr, B);

    int smem = (BT * KX + 64 * KX + BT * 129 + 2 * G4 + 2 * H + 2) * (int)sizeof(float); // ~78.5 KB
    cudaFuncSetAttribute(lstm_kernel, cudaFuncAttributeMaxDynamicSharedMemorySize, smem);
    lstm_kernel<<<B / BT, THREADS_R, smem>>>(W_out, b_out, out, B);
}

// round 14
// speedup vs baseline: 1.8626x; 1.8626x over previous
#include <cuda_runtime.h>
#include <cuda_bf16.h>
#include <math.h>
#include <stdint.h>
#include <stddef.h>

#define H      128
#define G4     512
#define T_OBS  8
#define PRED   12
#define NNB    64
#define EMB    32
#define NCELL  16
#define KF     18
#define KP     160          // K padded to 10 k-steps of 16
#define XPITCH 168          // X row pitch in bf16 elems (bank-conflict break)
#define GPITCH 520          // gates smem pitch in f32
#define BT     128          // batch rows per CTA
#define THREADS 512
#define BMAX   16384

// smem byte offsets
#define OFF_X1    0                         // 128*168 bf16 = 43008 B
#define OFF_X2    43008
#define OFF_GATES 86016                     // 32*520 f32 = 66560 B
#define OFF_BIAS  152576                    // 1024 f32
#define OFF_WOUT  156672                    // 258 f32 -> 1032 B
#define SMEM_REQ  157712

// ---------------- device scratch ----------------
__device__ __align__(128) unsigned short g_W[2 * G4 * KP];   // bf16 planes: [hi|lo][512][160]
__device__ __align__(128) float g_bias[2 * G4];
__device__ __align__(128) float g_feat[BMAX * T_OBS * KF];

__device__ __forceinline__ unsigned short bhi(float v) {
    return __bfloat16_as_ushort(__float2bfloat16_rn(v));
}
__device__ __forceinline__ float bval(unsigned short u) {
    return __bfloat162float(__ushort_as_bfloat16(u));
}
__device__ __forceinline__ void split2(float v0, float v1, uint32_t& hi, uint32_t& lo) {
    unsigned short h0 = bhi(v0), h1 = bhi(v1);
    hi = (uint32_t)h0 | ((uint32_t)h1 << 16);
    lo = (uint32_t)bhi(v0 - bval(h0)) | ((uint32_t)bhi(v1 - bval(h1)) << 16);
}
__device__ __forceinline__ float sigf(float x) {
    return __fdividef(1.0f, 1.0f + __expf(-x));
}
__device__ __forceinline__ float tanhfast(float x) {
    return 1.0f - __fdividef(2.0f, __expf(2.0f * x) + 1.0f);
}
// m16n8k16 row.col bf16 -> f32 (baseline sm_80 PTX; valid on compute_103)
__device__ __forceinline__ void mma16816(float* c, const uint32_t* a, const uint32_t* b) {
    asm volatile(
        "mma.sync.aligned.m16n8k16.row.col.f32.bf16.bf16.f32 "
        "{%0,%1,%2,%3}, {%4,%5,%6,%7}, {%8,%9}, {%0,%1,%2,%3};"
        : "+f"(c[0]), "+f"(c[1]), "+f"(c[2]), "+f"(c[3])
        : "r"(a[0]), "r"(a[1]), "r"(a[2]), "r"(a[3]), "r"(b[0]), "r"(b[1]));
}

// ---------------- kernel 1: fold + bf16-split weights (one warp per gate row) ----------------
__global__ void prep_kernel(const float* __restrict__ W_in, const float* __restrict__ b_in,
                            const float* __restrict__ W_sp, const float* __restrict__ b_sp,
                            const float* __restrict__ W_ih, const float* __restrict__ W_hh,
                            const float* __restrict__ b_ih, const float* __restrict__ b_hh,
                            const float* __restrict__ embed)
{
    __shared__ float buf[4][KP];
    int w = threadIdx.x >> 5, lane = threadIdx.x & 31;
    int g = blockIdx.x * 4 + w;
    if (g >= G4) return;

    for (int k = lane; k < KP; k += 32) buf[w][k] = 0.f;
    const float* wih = W_ih + (size_t)g * 256;
    const float* whh = W_hh + (size_t)g * H;
    for (int k = lane; k < H; k += 32) buf[w][k] = whh[k];

    float Ce = 0.f;
    #pragma unroll 4
    for (int jj = 0; jj < H; jj++) Ce += wih[H + jj] * W_sp[jj * EMB + lane];

    float a0 = 0.f, a1 = 0.f, s1 = 0.f, s2 = 0.f;
    for (int jj = lane; jj < H; jj += 32) {
        float w1 = wih[jj], w2 = wih[H + jj];
        a0 += w1 * W_in[jj * 2 + 0];
        a1 += w1 * W_in[jj * 2 + 1];
        s1 += w1 * b_in[jj];
        s2 += w2 * b_sp[jj];
    }
    #pragma unroll
    for (int off = 16; off; off >>= 1) {
        a0 += __shfl_xor_sync(0xffffffffu, a0, off);
        a1 += __shfl_xor_sync(0xffffffffu, a1, off);
        s1 += __shfl_xor_sync(0xffffffffu, s1, off);
        s2 += __shfl_xor_sync(0xffffffffu, s2, off);
    }
    for (int c = 0; c < NCELL; c++) {
        float v = Ce * embed[c * EMB + lane];
        #pragma unroll
        for (int off = 16; off; off >>= 1) v += __shfl_xor_sync(0xffffffffu, v, off);
        if (lane == 0) buf[w][H + 2 + c] = v;
    }
    if (lane == 0) {
        buf[w][H + 0] = a0; buf[w][H + 1] = a1;
        float bb = b_ih[g] + b_hh[g] + s1;
        g_bias[g]      = bb + s2;   // obs steps (social bias present)
        g_bias[G4 + g] = bb;        // pred steps (social half exactly zero)
    }
    __syncwarp();

    for (int k = lane; k < KP; k += 32) {
        float v = buf[w][k];
        unsigned short h16 = bhi(v);
        unsigned short l16 = bhi(v - bval(h16));
        g_W[(size_t)g * KP + k]        = h16;
        g_W[(size_t)(G4 + g) * KP + k] = l16;
    }
}

// ---------------- kernel 2: neighbor histogram -> feat (validated) ----------------
__global__ void hist_kernel(const float* __restrict__ obs, const float* __restrict__ nbr, int B)
{
    __shared__ int cnt[4][T_OBS][NCELL];
    int w = threadIdx.x >> 5, lane = threadIdx.x & 31;
    int b = blockIdx.x * 4 + w;

    for (int i = threadIdx.x; i < 4 * T_OBS * NCELL; i += blockDim.x) ((int*)cnt)[i] = 0;
    __syncthreads();

    if (b < B) {
        float of[16];
        const float4* op = (const float4*)(obs + (size_t)b * T_OBS * 2);
        #pragma unroll
        for (int q = 0; q < 4; q++) {
            float4 v = op[q];
            of[4*q+0] = v.x; of[4*q+1] = v.y; of[4*q+2] = v.z; of[4*q+3] = v.w;
        }
        #pragma unroll
        for (int half = 0; half < 2; half++) {
            int nn = lane + half * 32;
            const float4* np = (const float4*)(nbr + ((size_t)b * NNB + nn) * T_OBS * 2);
            float nf[16];
            #pragma unroll
            for (int q = 0; q < 4; q++) {
                float4 v = np[q];
                nf[4*q+0] = v.x; nf[4*q+1] = v.y; nf[4*q+2] = v.z; nf[4*q+3] = v.w;
            }
            #pragma unroll
            for (int t = 0; t < T_OBS; t++) {
                float rx = nf[2*t+0] - of[2*t+0];
                float ry = nf[2*t+1] - of[2*t+1];
                int ix = (int)floorf(rx * 2.0f);
                int iy = (int)floorf(ry * 2.0f);
                ix = max(-2, min(1, ix)) + 2;
                iy = max(-2, min(1, iy)) + 2;
                atomicAdd(&cnt[w][t][ix * 4 + iy], 1);
            }
        }
    }
    __syncthreads();

    if (b < B) {
        for (int i = lane; i < T_OBS * KF; i += 32) {
            int t = i / KF, c = i % KF;
            float v = (c < 2) ? obs[((size_t)b * T_OBS + t) * 2 + c] : (float)cnt[w][t][c - 2];
            g_feat[((size_t)b * T_OBS + t) * KF + c] = v;
        }
    }
}

// ---------------- kernel 3: recurrent LSTM via mma.sync bf16 3-pass ----------------
__global__ void __launch_bounds__(THREADS, 1)
lstm_kernel(const float* __restrict__ W_out, const float* __restrict__ b_out,
            float* __restrict__ out, int B)
{
    extern __shared__ unsigned char sb[];
    unsigned short* X1   = (unsigned short*)(sb + OFF_X1);
    unsigned short* X2   = (unsigned short*)(sb + OFF_X2);
    float*          gsm  = (float*)(sb + OFF_GATES);
    float*          shBias = (float*)(sb + OFF_BIAS);
    float*          shWout = (float*)(sb + OFF_WOUT);

    const int tid  = threadIdx.x;
    const int w    = tid >> 5, lane = tid & 31;
    const int gid  = lane >> 2;            // mma group id (0..7)
    const int tig2 = (lane & 3) * 2;       // 2*thread-in-group
    const int ncol0 = w * 32;              // warp's 32 gate-cols
    const int erow = tid >> 4;             // epilogue local row (0..31)
    const int ejb  = (tid & 15) * 8;       // epilogue j-base
    const int gb0  = blockIdx.x * BT;

    // zero X planes (incl. padding cols), load bias + W_out
    for (int i = tid; i < 2 * BT * XPITCH / 2; i += THREADS) ((uint32_t*)X1)[i] = 0u;
    for (int i = tid; i < 2 * G4; i += THREADS) shBias[i] = g_bias[i];
    for (int i = tid; i < 2 * H; i += THREADS) shWout[i] = W_out[i];
    if (tid == 0) { shWout[256] = b_out[0]; shWout[257] = b_out[1]; }

    float cst[32];                         // c-state: [quarter][jj]
    #pragma unroll
    for (int i = 0; i < 32; i++) cst[i] = 0.f;

    const unsigned short* Whi = g_W;
    const unsigned short* Wlo = g_W + (size_t)G4 * KP;
    __syncthreads();

    for (int step = 0; step < T_OBS + PRED; step++) {
        const bool isObs = (step < T_OBS);

        // stage small-x features (cols 128..145) as bf16 hi/lo
        if (isObs) {
            for (int i = tid; i < BT * 9; i += THREADS) {
                int rr = i / 9, pi = i % 9;
                const float* fp = g_feat + ((size_t)(gb0 + rr) * T_OBS + step) * KF + pi * 2;
                uint32_t hi, lo; split2(fp[0], fp[1], hi, lo);
                int e = rr * XPITCH + H + pi * 2;
                *(uint32_t*)&X1[e] = hi;
                *(uint32_t*)&X2[e] = lo;
            }
        } else if (step == T_OBS) {
            for (int i = tid; i < BT * 9; i += THREADS) {
                int rr = i / 9, pi = i % 9;
                int e = rr * XPITCH + H + pi * 2;
                *(uint32_t*)&X1[e] = 0u;
                *(uint32_t*)&X2[e] = 0u;
            }
        }
        const float* biasp = shBias + (isObs ? 0 : G4);
        __syncthreads();

        // ---- 4 row-quarters of 32: GEMM (3-pass bf16 split) -> gates smem -> epilogue ----
        #pragma unroll
        for (int q = 0; q < 4; q++) {
            float C[2][4][4];
            #pragma unroll
            for (int mf = 0; mf < 2; mf++)
                #pragma unroll
                for (int nf = 0; nf < 4; nf++)
                    #pragma unroll
                    for (int i = 0; i < 4; i++) C[mf][nf][i] = 0.f;

            const int arow = q * 32 + gid;
            #pragma unroll
            for (int pass = 0; pass < 3; pass++) {
                const unsigned short* Xs = (pass < 2) ? X1 : X2;
                const unsigned short* Ws = (pass == 1) ? Wlo : Whi;
                #pragma unroll 2
                for (int ks = 0; ks < KP / 16; ks++) {
                    const int kk = ks * 16 + tig2;
                    uint32_t a[2][4];
                    #pragma unroll
                    for (int mf = 0; mf < 2; mf++) {
                        const unsigned short* xr = Xs + (arow + mf * 16) * XPITCH + kk;
                        a[mf][0] = *(const uint32_t*)(xr);
                        a[mf][1] = *(const uint32_t*)(xr + 8 * XPITCH);
                        a[mf][2] = *(const uint32_t*)(xr + 8);
                        a[mf][3] = *(const uint32_t*)(xr + 8 * XPITCH + 8);
                    }
                    uint32_t bb[4][2];
                    #pragma unroll
                    for (int nf = 0; nf < 4; nf++) {
                        const unsigned short* wr = Ws + (size_t)(ncol0 + nf * 8 + gid) * KP + kk;
                        bb[nf][0] = *(const uint32_t*)(wr);
                        bb[nf][1] = *(const uint32_t*)(wr + 8);
                    }
                    #pragma unroll
                    for (int mf = 0; mf < 2; mf++)
                        #pragma unroll
                        for (int nf = 0; nf < 4; nf++)
                            mma16816(C[mf][nf], a[mf], bb[nf]);
                }
            }
            // store C fragments to gates smem
            #pragma unroll
            for (int mf = 0; mf < 2; mf++)
                #pragma unroll
                for (int nf = 0; nf < 4; nf++) {
                    int col = ncol0 + nf * 8 + tig2;
                    int r = mf * 16 + gid;
                    *(float2*)&gsm[r * GPITCH + col]       = make_float2(C[mf][nf][0], C[mf][nf][1]);
                    *(float2*)&gsm[(r + 8) * GPITCH + col] = make_float2(C[mf][nf][2], C[mf][nf][3]);
                }
            __syncthreads();

            // epilogue: thread owns (row = q*32+erow, j = ejb..ejb+7)
            const int grow = q * 32 + erow;
            float hv[8];
            #pragma unroll
            for (int jj = 0; jj < 8; jj++) {
                int j = ejb + jj;
                float vi = gsm[erow * GPITCH + j]           + biasp[j];
                float vf = gsm[erow * GPITCH + H + j]       + biasp[H + j];
                float vg = gsm[erow * GPITCH + 2 * H + j]   + biasp[2 * H + j];
                float vo = gsm[erow * GPITCH + 3 * H + j]   + biasp[3 * H + j];
                float c = cst[q * 8 + jj];
                c = sigf(vf) * c + sigf(vi) * tanhfast(vg);
                cst[q * 8 + jj] = c;
                hv[jj] = sigf(vo) * tanhfast(c);
            }
            #pragma unroll
            for (int jj = 0; jj < 8; jj += 2) {
                uint32_t hi, lo; split2(hv[jj], hv[jj + 1], hi, lo);
                int e = grow * XPITCH + ejb + jj;
                *(uint32_t*)&X1[e] = hi;
                *(uint32_t*)&X2[e] = lo;
            }
            if (!isObs) {
                float d0 = 0.f, d1 = 0.f;
                #pragma unroll
                for (int jj = 0; jj < 8; jj++) {
                    d0 += hv[jj] * shWout[ejb + jj];
                    d1 += hv[jj] * shWout[H + ejb + jj];
                }
                #pragma unroll
                for (int off = 8; off; off >>= 1) {
                    d0 += __shfl_down_sync(0xffffffffu, d0, off, 16);
                    d1 += __shfl_down_sync(0xffffffffu, d1, off, 16);
                }
                if ((tid & 15) == 0) {
                    d0 += shWout[256]; d1 += shWout[257];
                    int p = step - T_OBS;
                    size_t ob = ((size_t)(gb0 + grow) * PRED + p) * 2;
                    out[ob] = d0; out[ob + 1] = d1;
                    uint32_t hi, lo; split2(d0, d1, hi, lo);   // feed back as prev
                    *(uint32_t*)&X1[grow * XPITCH + H] = hi;
                    *(uint32_t*)&X2[grow * XPITCH + H] = lo;
                }
            }
            __syncthreads();
        }
    }
}

// ---------------- launch ----------------
extern "C" void kernel_launch(void* const* d_in, const int* in_sizes, int n_in,
                              void* d_out, int out_size)
{
    const float* obs   = (const float*)d_in[0];
    const float* nbr   = (const float*)d_in[1];
    const float* embed = (const float*)d_in[2];
    const float* W_in  = (const float*)d_in[3];
    const float* b_in  = (const float*)d_in[4];
    const float* W_sp  = (const float*)d_in[5];
    const float* b_sp  = (const float*)d_in[6];
    const float* W_ih  = (const float*)d_in[7];
    const float* W_hh  = (const float*)d_in[8];
    const float* b_ih  = (const float*)d_in[9];
    const float* b_hh  = (const float*)d_in[10];
    const float* W_out = (const float*)d_in[11];
    const float* b_out = (const float*)d_in[12];
    float* out = (float*)d_out;

    int B = in_sizes[0] / (T_OBS * 2);

    prep_kernel<<<G4 / 4, 128>>>(W_in, b_in, W_sp, b_sp, W_ih, W_hh, b_ih, b_hh, embed);
    hist_kernel<<<(B + 3) / 4, 128>>>(obs, nbr, B);

    cudaFuncSetAttribute(lstm_kernel, cudaFuncAttributeMaxDynamicSharedMemorySize, SMEM_REQ);
    lstm_kernel<<<B / BT, THREADS, SMEM_REQ>>>(W_out, b_out, out, B);
}

// round 15
// speedup vs baseline: 4.3976x; 2.3609x over previous
#include <cuda_runtime.h>
#include <cuda_bf16.h>
#include <math.h>
#include <stdint.h>
#include <stddef.h>

#define H      128
#define G4     512
#define T_OBS  8
#define PRED   12
#define NNB    64
#define EMB    32
#define NCELL  16
#define KF     18
#define KP     160          // K padded to 10 k-steps of 16
#define NKS    10
#define XPITCH 168          // X row pitch in bf16 elems (bank-conflict break: 20r mod 32 distinct)
#define PS     (128 * XPITCH)   // plane stride in ushorts = 21504
#define BT     128          // batch rows per CTA
#define THREADS 512
#define BMAX   16384

// smem byte offsets
#define OFF_X     0                        // 2 buf x 2 planes x 128 x 168 bf16 = 172032 B
#define XBUF_B    86016                    // buffer stride bytes
#define OFF_RED   172032                   // 16 warps x 128 rows x 2 f32 = 16384 B
#define OFF_BIAS  188416                   // 1024 f32 = 4096 B
#define OFF_WOUT  192512                   // 258 f32 -> 1056 B
#define SMEM_REQ  193568

// ---------------- device scratch ----------------
// W in fragment order: [plane(hi/lo)][ks][col(512)][tig(4)] uint2 = {k2t,k2t+1 | k8+2t,k8+2t+1}
__device__ __align__(128) uint2 g_Wf[2 * NKS * G4 * 4];
__device__ __align__(128) float g_bias[2 * G4];
__device__ __align__(128) float g_feat[BMAX * T_OBS * KF];

__device__ __forceinline__ unsigned short bhi(float v) {
    return __bfloat16_as_ushort(__float2bfloat16_rn(v));
}
__device__ __forceinline__ float bval(unsigned short u) {
    return __bfloat162float(__ushort_as_bfloat16(u));
}
__device__ __forceinline__ void split2(float v0, float v1, uint32_t& hi, uint32_t& lo) {
    unsigned short h0 = bhi(v0), h1 = bhi(v1);
    hi = (uint32_t)h0 | ((uint32_t)h1 << 16);
    lo = (uint32_t)bhi(v0 - bval(h0)) | ((uint32_t)bhi(v1 - bval(h1)) << 16);
}
__device__ __forceinline__ float sigf(float x) {
    return __fdividef(1.0f, 1.0f + __expf(-x));
}
__device__ __forceinline__ float tanhfast(float x) {
    return 1.0f - __fdividef(2.0f, __expf(2.0f * x) + 1.0f);
}
__device__ __forceinline__ uint32_t smem_u32(const void* p) {
    uint32_t a;
    asm("{ .reg .u64 t; cvta.to.shared.u64 t, %1; cvt.u32.u64 %0, t; }" : "=r"(a) : "l"(p));
    return a;
}
__device__ __forceinline__ void mma4(float* c, const uint32_t* a, uint32_t b0, uint32_t b1) {
    asm volatile(
        "mma.sync.aligned.m16n8k16.row.col.f32.bf16.bf16.f32 "
        "{%0,%1,%2,%3}, {%4,%5,%6,%7}, {%8,%9}, {%0,%1,%2,%3};"
        : "+f"(c[0]), "+f"(c[1]), "+f"(c[2]), "+f"(c[3])
        : "r"(a[0]), "r"(a[1]), "r"(a[2]), "r"(a[3]), "r"(b0), "r"(b1));
}
#define LDM4(r, a) \
    asm volatile("ldmatrix.sync.aligned.m8n8.x4.shared.b16 {%0,%1,%2,%3}, [%4];" \
        : "=r"((r)[0]), "=r"((r)[1]), "=r"((r)[2]), "=r"((r)[3]) : "r"(a))

// ---------------- kernel 1: fold + bf16-split weights into fragment order ----------------
__global__ void prep_kernel(const float* __restrict__ W_in, const float* __restrict__ b_in,
                            const float* __restrict__ W_sp, const float* __restrict__ b_sp,
                            const float* __restrict__ W_ih, const float* __restrict__ W_hh,
                            const float* __restrict__ b_ih, const float* __restrict__ b_hh,
                            const float* __restrict__ embed)
{
    __shared__ float buf[4][KP];
    int w = threadIdx.x >> 5, lane = threadIdx.x & 31;
    int g = blockIdx.x * 4 + w;
    if (g >= G4) return;

    for (int k = lane; k < KP; k += 32) buf[w][k] = 0.f;
    const float* wih = W_ih + (size_t)g * 256;
    const float* whh = W_hh + (size_t)g * H;
    for (int k = lane; k < H; k += 32) buf[w][k] = whh[k];

    float Ce = 0.f;
    #pragma unroll 4
    for (int jj = 0; jj < H; jj++) Ce += wih[H + jj] * W_sp[jj * EMB + lane];

    float a0 = 0.f, a1 = 0.f, s1 = 0.f, s2 = 0.f;
    for (int jj = lane; jj < H; jj += 32) {
        float w1 = wih[jj], w2 = wih[H + jj];
        a0 += w1 * W_in[jj * 2 + 0];
        a1 += w1 * W_in[jj * 2 + 1];
        s1 += w1 * b_in[jj];
        s2 += w2 * b_sp[jj];
    }
    #pragma unroll
    for (int off = 16; off; off >>= 1) {
        a0 += __shfl_xor_sync(0xffffffffu, a0, off);
        a1 += __shfl_xor_sync(0xffffffffu, a1, off);
        s1 += __shfl_xor_sync(0xffffffffu, s1, off);
        s2 += __shfl_xor_sync(0xffffffffu, s2, off);
    }
    for (int c = 0; c < NCELL; c++) {
        float v = Ce * embed[c * EMB + lane];
        #pragma unroll
        for (int off = 16; off; off >>= 1) v += __shfl_xor_sync(0xffffffffu, v, off);
        if (lane == 0) buf[w][H + 2 + c] = v;
    }
    if (lane == 0) {
        buf[w][H + 0] = a0; buf[w][H + 1] = a1;
        float bb = b_ih[g] + b_hh[g] + s1;
        g_bias[g]      = bb + s2;   // obs steps
        g_bias[G4 + g] = bb;        // pred steps
    }
    __syncwarp();

    // fragment-order pack: per (ks, tig): {k0,k0+1} and {k0+8,k0+9}
    for (int i = lane; i < NKS * 4; i += 32) {
        int ks = i >> 2, tg = i & 3;
        int k0 = ks * 16 + tg * 2;
        float v00 = buf[w][k0],     v01 = buf[w][k0 + 1];
        float v10 = buf[w][k0 + 8], v11 = buf[w][k0 + 9];
        unsigned short h00 = bhi(v00), h01 = bhi(v01), h10 = bhi(v10), h11 = bhi(v11);
        uint2 hi, lo;
        hi.x = (uint32_t)h00 | ((uint32_t)h01 << 16);
        hi.y = (uint32_t)h10 | ((uint32_t)h11 << 16);
        lo.x = (uint32_t)bhi(v00 - bval(h00)) | ((uint32_t)bhi(v01 - bval(h01)) << 16);
        lo.y = (uint32_t)bhi(v10 - bval(h10)) | ((uint32_t)bhi(v11 - bval(h11)) << 16);
        g_Wf[(ks * G4 + g) * 4 + tg]                  = hi;
        g_Wf[NKS * G4 * 4 + (ks * G4 + g) * 4 + tg]   = lo;
    }
}

// ---------------- kernel 2: neighbor histogram -> feat (validated) ----------------
__global__ void hist_kernel(const float* __restrict__ obs, const float* __restrict__ nbr, int B)
{
    __shared__ int cnt[4][T_OBS][NCELL];
    int w = threadIdx.x >> 5, lane = threadIdx.x & 31;
    int b = blockIdx.x * 4 + w;

    for (int i = threadIdx.x; i < 4 * T_OBS * NCELL; i += blockDim.x) ((int*)cnt)[i] = 0;
    __syncthreads();

    if (b < B) {
        float of[16];
        const float4* op = (const float4*)(obs + (size_t)b * T_OBS * 2);
        #pragma unroll
        for (int q = 0; q < 4; q++) {
            float4 v = op[q];
            of[4*q+0] = v.x; of[4*q+1] = v.y; of[4*q+2] = v.z; of[4*q+3] = v.w;
        }
        #pragma unroll
        for (int half = 0; half < 2; half++) {
            int nn = lane + half * 32;
            const float4* np = (const float4*)(nbr + ((size_t)b * NNB + nn) * T_OBS * 2);
            float nf[16];
            #pragma unroll
            for (int q = 0; q < 4; q++) {
                float4 v = np[q];
                nf[4*q+0] = v.x; nf[4*q+1] = v.y; nf[4*q+2] = v.z; nf[4*q+3] = v.w;
            }
            #pragma unroll
            for (int t = 0; t < T_OBS; t++) {
                float rx = nf[2*t+0] - of[2*t+0];
                float ry = nf[2*t+1] - of[2*t+1];
                int ix = (int)floorf(rx * 2.0f);
                int iy = (int)floorf(ry * 2.0f);
                ix = max(-2, min(1, ix)) + 2;
                iy = max(-2, min(1, iy)) + 2;
                atomicAdd(&cnt[w][t][ix * 4 + iy], 1);
            }
        }
    }
    __syncthreads();

    if (b < B) {
        for (int i = lane; i < T_OBS * KF; i += 32) {
            int t = i / KF, c = i % KF;
            float v = (c < 2) ? obs[((size_t)b * T_OBS + t) * 2 + c] : (float)cnt[w][t][c - 2];
            g_feat[((size_t)b * T_OBS + t) * KF + c] = v;
        }
    }
}

// ---------------- kernel 3: register-epilogue mma.sync LSTM ----------------
// Warp w owns gate cols {g*128 + w*8 .. +7} for all gates g -> each thread's C frags
// hold i,f,g,o for the same (row, j) pairs. Double-buffered X planes (cur/nxt).
__global__ void __launch_bounds__(THREADS, 1)
lstm_kernel(const float* __restrict__ W_out, const float* __restrict__ b_out,
            float* __restrict__ out, int B)
{
    extern __shared__ unsigned char sb[];
    unsigned short* XS   = (unsigned short*)(sb + OFF_X);
    float* shRed  = (float*)(sb + OFF_RED);
    float* shBias = (float*)(sb + OFF_BIAS);
    float* shWout = (float*)(sb + OFF_WOUT);

    const int tid  = threadIdx.x;
    const int w    = tid >> 5, lane = tid & 31;
    const int gid  = lane >> 2, tig = lane & 3;
    const int j0   = w * 8;
    const int gb0  = blockIdx.x * BT;
    const uint32_t xsm = smem_u32(XS);
    // ldmatrix per-lane address core: row = lane&15, col-half = (lane>>4)*8
    const uint32_t ldm_off = (uint32_t)(((lane & 15) * XPITCH + (lane >> 4) * 8) * 2);
    const int wthr = (j0 + gid) * 4 + tig;    // W fragment index core

    for (int i = tid; i < (2 * XBUF_B) / 4; i += THREADS) ((uint32_t*)XS)[i] = 0u;
    for (int i = tid; i < 2 * G4; i += THREADS) shBias[i] = g_bias[i];
    for (int i = tid; i < 2 * H; i += THREADS) shWout[i] = W_out[i];
    if (tid == 0) { shWout[256] = b_out[0]; shWout[257] = b_out[1]; }

    float cst[32];                            // [blk][mf][rh][jj]
    #pragma unroll
    for (int i = 0; i < 32; i++) cst[i] = 0.f;

    __syncthreads();

    for (int step = 0; step < T_OBS + PRED; step++) {
        const bool isObs = (step < T_OBS);
        const int cur = step & 1, nxt = cur ^ 1;
        unsigned short* Xc1 = XS + cur * (2 * PS);
        unsigned short* Xc2 = Xc1 + PS;
        unsigned short* Xn1 = XS + nxt * (2 * PS);
        unsigned short* Xn2 = Xn1 + PS;

        // stage features into cur buffer cols 128..145
        if (isObs) {
            for (int i = tid; i < BT * 9; i += THREADS) {
                int rr = i / 9, pi = i % 9;
                const float* fp = g_feat + ((size_t)(gb0 + rr) * T_OBS + step) * KF + pi * 2;
                uint32_t hi, lo; split2(fp[0], fp[1], hi, lo);
                int e = rr * XPITCH + H + pi * 2;
                *(uint32_t*)&Xc1[e] = hi;
                *(uint32_t*)&Xc2[e] = lo;
            }
        } else if (step == T_OBS) {
            // zero prev+counts cols in BOTH buffers (safe: step-7 readers passed end-sync)
            for (int i = tid; i < 2 * 2 * BT * 9; i += THREADS) {
                int pl = i / (BT * 9), rem = i % (BT * 9);
                int rr = rem / 9, pi = rem % 9;
                *(uint32_t*)&XS[pl * PS + rr * XPITCH + H + pi * 2] = 0u;
            }
        }
        // per-thread bias + Wout regs for this step's j's
        const float* biasp = shBias + (isObs ? 0 : G4);
        float br[4][2], wo0[2], wo1[2];
        #pragma unroll
        for (int g = 0; g < 4; g++) {
            br[g][0] = biasp[g * H + j0 + 2 * tig];
            br[g][1] = biasp[g * H + j0 + 2 * tig + 1];
        }
        wo0[0] = shWout[j0 + 2 * tig];     wo0[1] = shWout[j0 + 2 * tig + 1];
        wo1[0] = shWout[H + j0 + 2 * tig]; wo1[1] = shWout[H + j0 + 2 * tig + 1];
        __syncthreads();

        // ---- 4 M-blocks of 32 rows; register epilogue per block, no barriers ----
        #pragma unroll
        for (int blk = 0; blk < 4; blk++) {
            float C[2][4][4];
            #pragma unroll
            for (int mf = 0; mf < 2; mf++)
                #pragma unroll
                for (int g = 0; g < 4; g++)
                    #pragma unroll
                    for (int i = 0; i < 4; i++) C[mf][g][i] = 0.f;

            uint32_t aX = xsm + (uint32_t)cur * XBUF_B + (uint32_t)(blk * 32 * XPITCH * 2) + ldm_off;

            #pragma unroll 2
            for (int ks = 0; ks < NKS; ks++) {
                uint32_t a1m0[4], a1m1[4], a2m0[4], a2m1[4];
                uint32_t a = aX + ks * 32;
                LDM4(a1m0, a);
                LDM4(a1m1, a + 16 * XPITCH * 2);
                LDM4(a2m0, a + PS * 2);
                LDM4(a2m1, a + PS * 2 + 16 * XPITCH * 2);
                const uint2* wp = g_Wf + ks * (G4 * 4) + wthr;
                #pragma unroll
                for (int g = 0; g < 4; g++) {
                    uint2 wh = wp[g * 512];
                    uint2 wl = wp[NKS * G4 * 4 + g * 512];
                    mma4(C[0][g], a1m0, wh.x, wh.y);
                    mma4(C[1][g], a1m1, wh.x, wh.y);
                    mma4(C[0][g], a1m0, wl.x, wl.y);
                    mma4(C[1][g], a1m1, wl.x, wl.y);
                    mma4(C[0][g], a2m0, wh.x, wh.y);
                    mma4(C[1][g], a2m1, wh.x, wh.y);
                }
            }

            // register epilogue: thread owns (row, j0+2tig..+1) for 4 rows of this block
            #pragma unroll
            for (int mf = 0; mf < 2; mf++)
                #pragma unroll
                for (int rh = 0; rh < 2; rh++) {
                    int row = blk * 32 + mf * 16 + rh * 8 + gid;
                    float hv[2];
                    #pragma unroll
                    for (int jj = 0; jj < 2; jj++) {
                        int ci = rh * 2 + jj;
                        float vi = C[mf][0][ci] + br[0][jj];
                        float vf = C[mf][1][ci] + br[1][jj];
                        float vg = C[mf][2][ci] + br[2][jj];
                        float vo = C[mf][3][ci] + br[3][jj];
                        int s = ((blk * 2 + mf) * 2 + rh) * 2 + jj;
                        float c = cst[s];
                        c = sigf(vf) * c + sigf(vi) * tanhfast(vg);
                        cst[s] = c;
                        hv[jj] = sigf(vo) * tanhfast(c);
                    }
                    uint32_t hi, lo; split2(hv[0], hv[1], hi, lo);
                    int e = row * XPITCH + j0 + 2 * tig;
                    *(uint32_t*)&Xn1[e] = hi;
                    *(uint32_t*)&Xn2[e] = lo;
                    if (!isObs) {
                        float pd0 = hv[0] * wo0[0] + hv[1] * wo0[1];
                        float pd1 = hv[0] * wo1[0] + hv[1] * wo1[1];
                        pd0 += __shfl_xor_sync(0xffffffffu, pd0, 1);
                        pd0 += __shfl_xor_sync(0xffffffffu, pd0, 2);
                        pd1 += __shfl_xor_sync(0xffffffffu, pd1, 1);
                        pd1 += __shfl_xor_sync(0xffffffffu, pd1, 2);
                        if (tig == 0)
                            *(float2*)&shRed[(w * BT + row) * 2] = make_float2(pd0, pd1);
                    }
                }
        }

        if (!isObs) {
            __syncthreads();
            if (tid < BT) {
                float d0 = shWout[256], d1 = shWout[257];
                #pragma unroll
                for (int ww = 0; ww < 16; ww++) {
                    float2 v = *(float2*)&shRed[(ww * BT + tid) * 2];
                    d0 += v.x; d1 += v.y;
                }
                int p = step - T_OBS;
                *(float2*)&out[((size_t)(gb0 + tid) * PRED + p) * 2] = make_float2(d0, d1);
                uint32_t hi, lo; split2(d0, d1, hi, lo);   // feed back as prev
                *(uint32_t*)&Xn1[tid * XPITCH + H] = hi;
                *(uint32_t*)&Xn2[tid * XPITCH + H] = lo;
            }
        }
        __syncthreads();   // end of step: all nxt writes visible
    }
}

// ---------------- launch ----------------
extern "C" void kernel_launch(void* const* d_in, const int* in_sizes, int n_in,
                              void* d_out, int out_size)
{
    const float* obs   = (const float*)d_in[0];
    const float* nbr   = (const float*)d_in[1];
    const float* embed = (const float*)d_in[2];
    const float* W_in  = (const float*)d_in[3];
    const float* b_in  = (const float*)d_in[4];
    const float* W_sp  = (const float*)d_in[5];
    const float* b_sp  = (const float*)d_in[6];
    const float* W_ih  = (const float*)d_in[7];
    const float* W_hh  = (const float*)d_in[8];
    const float* b_ih  = (const float*)d_in[9];
    const float* b_hh  = (const float*)d_in[10];
    const float* W_out = (const float*)d_in[11];
    const float* b_out = (const float*)d_in[12];
    float* out = (float*)d_out;

    int B = in_sizes[0] / (T_OBS * 2);

    prep_kernel<<<G4 / 4, 128>>>(W_in, b_in, W_sp, b_sp, W_ih, W_hh, b_ih, b_hh, embed);
    hist_kernel<<<(B + 3) / 4, 128>>>(obs, nbr, B);

    cudaFuncSetAttribute(lstm_kernel, cudaFuncAttributeMaxDynamicSharedMemorySize, SMEM_REQ);
    lstm_kernel<<<B / BT, THREADS, SMEM_REQ>>>(W_out, b_out, out, B);
}

// round 17
// speedup vs baseline: 5.6651x; 1.2882x over previous
#include <cuda_runtime.h>
#include <cuda_bf16.h>
#include <math.h>
#include <stdint.h>
#include <stddef.h>

#define H      128
#define G4     512
#define T_OBS  8
#define PRED   12
#define NNB    64
#define EMB    32
#define NCELL  16
#define KF     18
#define KP     144          // K: h(128) + counts(16); 9 k-steps of 16
#define NKS    9
#define XPITCH 152          // X row pitch in bf16 elems (76 words; 12r mod 32 distinct)
#define PS     (128 * XPITCH)   // plane stride in ushorts = 19456
#define BT     128          // batch rows per CTA
#define THREADS 512
#define BMAX   16384

// smem byte offsets
#define OFF_X     0                        // 2 buf x 2 planes x 128 x 152 bf16 = 155648 B
#define XBUF_B    77824                    // buffer stride bytes (2 planes)
#define OFF_RED   155648                   // 16 warps x 128 rows x 2 f32 = 16384 B
#define OFF_BIAS  172032                   // 1024 f32 = 4096 B
#define OFF_WOUT  176128                   // 258 f32 -> 1056 B
#define OFF_AX    177184                   // 512 f32 = 2048 B
#define OFF_AY    179232                   // 512 f32 = 2048 B
#define OFF_PXY   181280                   // 128 float2 = 1024 B
#define SMEM_REQ  182336

// ---------------- device scratch ----------------
// W fragments: [ks(9)][col(512)][tig(4)] uint4 = {hi_b0, hi_b1, lo_b0, lo_b1}
__device__ __align__(128) uint4 g_Wf4[NKS * G4 * 4];
__device__ __align__(128) float g_bias[2 * G4];
__device__ __align__(128) float g_Ax[G4];
__device__ __align__(128) float g_Ay[G4];
__device__ __align__(128) float g_feat[BMAX * T_OBS * KF];

__device__ __forceinline__ unsigned short bhi(float v) {
    return __bfloat16_as_ushort(__float2bfloat16_rn(v));
}
__device__ __forceinline__ float bval(unsigned short u) {
    return __bfloat162float(__ushort_as_bfloat16(u));
}
__device__ __forceinline__ void split2(float v0, float v1, uint32_t& hi, uint32_t& lo) {
    unsigned short h0 = bhi(v0), h1 = bhi(v1);
    hi = (uint32_t)h0 | ((uint32_t)h1 << 16);
    lo = (uint32_t)bhi(v0 - bval(h0)) | ((uint32_t)bhi(v1 - bval(h1)) << 16);
}
__device__ __forceinline__ float sigf(float x) {
    return __fdividef(1.0f, 1.0f + __expf(-x));
}
__device__ __forceinline__ float tanhfast(float x) {
    return 1.0f - __fdividef(2.0f, __expf(2.0f * x) + 1.0f);
}
__device__ __forceinline__ uint32_t smem_u32(const void* p) {
    uint32_t a;
    asm("{ .reg .u64 t; cvta.to.shared.u64 t, %1; cvt.u32.u64 %0, t; }" : "=r"(a) : "l"(p));
    return a;
}
__device__ __forceinline__ void mma4(float* c, const uint32_t* a, uint32_t b0, uint32_t b1) {
    asm volatile(
        "mma.sync.aligned.m16n8k16.row.col.f32.bf16.bf16.f32 "
        "{%0,%1,%2,%3}, {%4,%5,%6,%7}, {%8,%9}, {%0,%1,%2,%3};"
        : "+f"(c[0]), "+f"(c[1]), "+f"(c[2]), "+f"(c[3])
        : "r"(a[0]), "r"(a[1]), "r"(a[2]), "r"(a[3]), "r"(b0), "r"(b1));
}
#define LDM4(r, a) \
    asm volatile("ldmatrix.sync.aligned.m8n8.x4.shared.b16 {%0,%1,%2,%3}, [%4];" \
        : "=r"((r)[0]), "=r"((r)[1]), "=r"((r)[2]), "=r"((r)[3]) : "r"(a))
#define LDM2(r, a) \
    asm volatile("ldmatrix.sync.aligned.m8n8.x2.shared.b16 {%0,%1}, [%2];" \
        : "=r"((r)[0]), "=r"((r)[1]) : "r"(a))

// ---------------- kernel 1: fold + bf16-split weights into uint4 fragment order ----------------
__global__ void prep_kernel(const float* __restrict__ W_in, const float* __restrict__ b_in,
                            const float* __restrict__ W_sp, const float* __restrict__ b_sp,
                            const float* __restrict__ W_ih, const float* __restrict__ W_hh,
                            const float* __restrict__ b_ih, const float* __restrict__ b_hh,
                            const float* __restrict__ embed)
{
    __shared__ float buf[4][KP];
    int w = threadIdx.x >> 5, lane = threadIdx.x & 31;
    int g = blockIdx.x * 4 + w;
    if (g >= G4) return;

    for (int k = lane; k < KP; k += 32) buf[w][k] = 0.f;
    const float* wih = W_ih + (size_t)g * 256;
    const float* whh = W_hh + (size_t)g * H;
    for (int k = lane; k < H; k += 32) buf[w][k] = whh[k];

    float Ce = 0.f;
    #pragma unroll 8
    for (int jj = 0; jj < H; jj++) Ce += wih[H + jj] * W_sp[jj * EMB + lane];

    float a0 = 0.f, a1 = 0.f, s1 = 0.f, s2 = 0.f;
    for (int jj = lane; jj < H; jj += 32) {
        float w1 = wih[jj], w2 = wih[H + jj];
        a0 += w1 * W_in[jj * 2 + 0];
        a1 += w1 * W_in[jj * 2 + 1];
        s1 += w1 * b_in[jj];
        s2 += w2 * b_sp[jj];
    }
    #pragma unroll
    for (int off = 16; off; off >>= 1) {
        a0 += __shfl_xor_sync(0xffffffffu, a0, off);
        a1 += __shfl_xor_sync(0xffffffffu, a1, off);
        s1 += __shfl_xor_sync(0xffffffffu, s1, off);
        s2 += __shfl_xor_sync(0xffffffffu, s2, off);
    }
    for (int c = 0; c < NCELL; c++) {
        float v = Ce * embed[c * EMB + lane];
        #pragma unroll
        for (int off = 16; off; off >>= 1) v += __shfl_xor_sync(0xffffffffu, v, off);
        if (lane == 0) buf[w][H + c] = v;     // counts cols 128..143
    }
    if (lane == 0) {
        g_Ax[g] = a0; g_Ay[g] = a1;           // rank-2 agent term (fp32, exact)
        float bb = b_ih[g] + b_hh[g] + s1;
        g_bias[g]      = bb + s2;             // obs steps
        g_bias[G4 + g] = bb;                  // pred steps
    }
    __syncwarp();

    // fragment pack: per (ks, tig): b0={k0,k0+1}, b1={k0+8,k0+9}, hi+lo planes in one uint4
    for (int i = lane; i < NKS * 4; i += 32) {
        int ks = i >> 2, tg = i & 3;
        int k0 = ks * 16 + tg * 2;
        float v00 = buf[w][k0],     v01 = buf[w][k0 + 1];
        float v10 = buf[w][k0 + 8], v11 = buf[w][k0 + 9];
        unsigned short h00 = bhi(v00), h01 = bhi(v01), h10 = bhi(v10), h11 = bhi(v11);
        uint4 fr;
        fr.x = (uint32_t)h00 | ((uint32_t)h01 << 16);
        fr.y = (uint32_t)h10 | ((uint32_t)h11 << 16);
        fr.z = (uint32_t)bhi(v00 - bval(h00)) | ((uint32_t)bhi(v01 - bval(h01)) << 16);
        fr.w = (uint32_t)bhi(v10 - bval(h10)) | ((uint32_t)bhi(v11 - bval(h11)) << 16);
        g_Wf4[(ks * G4 + g) * 4 + tg] = fr;
    }
}

// ---------------- kernel 2: neighbor histogram -> feat (validated) ----------------
__global__ void hist_kernel(const float* __restrict__ obs, const float* __restrict__ nbr, int B)
{
    __shared__ int cnt[4][T_OBS][NCELL];
    int w = threadIdx.x >> 5, lane = threadIdx.x & 31;
    int b = blockIdx.x * 4 + w;

    for (int i = threadIdx.x; i < 4 * T_OBS * NCELL; i += blockDim.x) ((int*)cnt)[i] = 0;
    __syncthreads();

    if (b < B) {
        float of[16];
        const float4* op = (const float4*)(obs + (size_t)b * T_OBS * 2);
        #pragma unroll
        for (int q = 0; q < 4; q++) {
            float4 v = op[q];
            of[4*q+0] = v.x; of[4*q+1] = v.y; of[4*q+2] = v.z; of[4*q+3] = v.w;
        }
        #pragma unroll
        for (int half = 0; half < 2; half++) {
            int nn = lane + half * 32;
            const float4* np = (const float4*)(nbr + ((size_t)b * NNB + nn) * T_OBS * 2);
            float nf[16];
            #pragma unroll
            for (int q = 0; q < 4; q++) {
                float4 v = np[q];
                nf[4*q+0] = v.x; nf[4*q+1] = v.y; nf[4*q+2] = v.z; nf[4*q+3] = v.w;
            }
            #pragma unroll
            for (int t = 0; t < T_OBS; t++) {
                float rx = nf[2*t+0] - of[2*t+0];
                float ry = nf[2*t+1] - of[2*t+1];
                int ix = (int)floorf(rx * 2.0f);
                int iy = (int)floorf(ry * 2.0f);
                ix = max(-2, min(1, ix)) + 2;
                iy = max(-2, min(1, iy)) + 2;
                atomicAdd(&cnt[w][t][ix * 4 + iy], 1);
            }
        }
    }
    __syncthreads();

    if (b < B) {
        for (int i = lane; i < T_OBS * KF; i += 32) {
            int t = i / KF, c = i % KF;
            float v = (c < 2) ? obs[((size_t)b * T_OBS + t) * 2 + c] : (float)cnt[w][t][c - 2];
            g_feat[((size_t)b * T_OBS + t) * KF + c] = v;
        }
    }
}

// ---------------- kernel 3: register-epilogue mma.sync LSTM (rank-2 agent term in fp32) ----------------
__global__ void __launch_bounds__(THREADS, 1)
lstm_kernel(const float* __restrict__ W_out, const float* __restrict__ b_out,
            float* __restrict__ out, int B)
{
    extern __shared__ unsigned char sb[];
    unsigned short* XS = (unsigned short*)(sb + OFF_X);
    float*  shRed  = (float*)(sb + OFF_RED);
    float*  shBias = (float*)(sb + OFF_BIAS);
    float*  shWout = (float*)(sb + OFF_WOUT);
    float*  shAx   = (float*)(sb + OFF_AX);
    float*  shAy   = (float*)(sb + OFF_AY);
    float2* shPXY  = (float2*)(sb + OFF_PXY);

    const int tid  = threadIdx.x;
    const int w    = tid >> 5, lane = tid & 31;
    const int gid  = lane >> 2, tig = lane & 3;
    const int j0   = w * 8;
    const int gb0  = blockIdx.x * BT;
    const uint32_t xsm = smem_u32(XS);
    const uint32_t ldm_off = (uint32_t)(((lane & 15) * XPITCH + (lane >> 4) * 8) * 2);
    const int wcol = j0 + gid;                 // W column core (gate col = g*128 + wcol)

    for (int i = tid; i < (2 * XBUF_B) / 4; i += THREADS) ((uint32_t*)XS)[i] = 0u;
    for (int i = tid; i < 2 * G4; i += THREADS) shBias[i] = g_bias[i];
    for (int i = tid; i < G4; i += THREADS) { shAx[i] = g_Ax[i]; shAy[i] = g_Ay[i]; }
    for (int i = tid; i < 2 * H; i += THREADS) shWout[i] = W_out[i];
    if (tid == 0) { shWout[256] = b_out[0]; shWout[257] = b_out[1]; }

    float cst[32];
    #pragma unroll
    for (int i = 0; i < 32; i++) cst[i] = 0.f;

    __syncthreads();

    // rank-2 agent weights for this thread's (g, j) set — step-invariant
    float Axl[4][2], Ayl[4][2];
    #pragma unroll
    for (int g = 0; g < 4; g++)
        #pragma unroll
        for (int jj = 0; jj < 2; jj++) {
            int gr = g * H + j0 + 2 * tig + jj;
            Axl[g][jj] = shAx[gr];
            Ayl[g][jj] = shAy[gr];
        }
    float wo0[2], wo1[2];
    wo0[0] = shWout[j0 + 2 * tig];     wo0[1] = shWout[j0 + 2 * tig + 1];
    wo1[0] = shWout[H + j0 + 2 * tig]; wo1[1] = shWout[H + j0 + 2 * tig + 1];

    for (int step = 0; step < T_OBS + PRED; step++) {
        const bool isObs = (step < T_OBS);
        const int cur = step & 1, nxt = cur ^ 1;
        unsigned short* Xc1 = XS + cur * (2 * PS);
        unsigned short* Xn1 = XS + nxt * (2 * PS);
        unsigned short* Xn2 = Xn1 + PS;

        // stage counts (exact in bf16 -> hi plane only; lo plane stays zero) + prev/obs xy
        if (isObs) {
            for (int i = tid; i < BT * 8; i += THREADS) {
                int rr = i >> 3, pi = i & 7;
                const float* fp = g_feat + ((size_t)(gb0 + rr) * T_OBS + step) * KF + 2 + pi * 2;
                uint32_t hi = (uint32_t)bhi(fp[0]) | ((uint32_t)bhi(fp[1]) << 16);
                *(uint32_t*)&Xc1[rr * XPITCH + H + pi * 2] = hi;
            }
            if (tid < BT) {
                const float* fp = g_feat + ((size_t)(gb0 + tid) * T_OBS + step) * KF;
                shPXY[tid] = make_float2(fp[0], fp[1]);
            }
        } else if (step == T_OBS) {
            if (tid < BT) shPXY[tid] = make_float2(0.f, 0.f);   // prev0 = 0
        }
        const float* biasp = shBias + (isObs ? 0 : G4);
        float br[4][2];
        #pragma unroll
        for (int g = 0; g < 4; g++) {
            br[g][0] = biasp[g * H + j0 + 2 * tig];
            br[g][1] = biasp[g * H + j0 + 2 * tig + 1];
        }
        __syncthreads();

        // ---- 4 M-blocks of 32 rows; register epilogue per block ----
        #pragma unroll
        for (int blk = 0; blk < 4; blk++) {
            float C[2][4][4];
            #pragma unroll
            for (int mf = 0; mf < 2; mf++)
                #pragma unroll
                for (int g = 0; g < 4; g++)
                    #pragma unroll
                    for (int i = 0; i < 4; i++) C[mf][g][i] = 0.f;

            uint32_t aX = xsm + (uint32_t)cur * XBUF_B + (uint32_t)(blk * 32 * XPITCH * 2) + ldm_off;

            // h columns: 8 ks, 3-pass bf16 split
            #pragma unroll 2
            for (int ks = 0; ks < 8; ks++) {
                uint32_t a1m0[4], a1m1[4], a2m0[4], a2m1[4];
                uint32_t a = aX + ks * 32;
                LDM4(a1m0, a);
                LDM4(a1m1, a + 16 * XPITCH * 2);
                LDM4(a2m0, a + PS * 2);
                LDM4(a2m1, a + PS * 2 + 16 * XPITCH * 2);
                #pragma unroll
                for (int g = 0; g < 4; g++) {
                    uint4 wv = __ldg(&g_Wf4[((size_t)ks * G4 + g * 128 + wcol) * 4 + tig]);
                    mma4(C[0][g], a1m0, wv.x, wv.y);
                    mma4(C[1][g], a1m1, wv.x, wv.y);
                    mma4(C[0][g], a1m0, wv.z, wv.w);
                    mma4(C[1][g], a1m1, wv.z, wv.w);
                    mma4(C[0][g], a2m0, wv.x, wv.y);
                    mma4(C[1][g], a2m1, wv.x, wv.y);
                }
            }
            // counts ks (obs only): x exact in bf16, hi plane only; W hi+lo
            if (isObs) {
                uint32_t a1m0[4], a1m1[4];
                uint32_t a = aX + 8 * 32;
                LDM4(a1m0, a);
                LDM4(a1m1, a + 16 * XPITCH * 2);
                #pragma unroll
                for (int g = 0; g < 4; g++) {
                    uint4 wv = __ldg(&g_Wf4[((size_t)8 * G4 + g * 128 + wcol) * 4 + tig]);
                    mma4(C[0][g], a1m0, wv.x, wv.y);
                    mma4(C[1][g], a1m1, wv.x, wv.y);
                    mma4(C[0][g], a1m0, wv.z, wv.w);
                    mma4(C[1][g], a1m1, wv.z, wv.w);
                }
            }

            // register epilogue
            #pragma unroll
            for (int mf = 0; mf < 2; mf++)
                #pragma unroll
                for (int rh = 0; rh < 2; rh++) {
                    int row = blk * 32 + mf * 16 + rh * 8 + gid;
                    float2 pxy = shPXY[row];
                    float hv[2];
                    #pragma unroll
                    for (int jj = 0; jj < 2; jj++) {
                        int ci = rh * 2 + jj;
                        float vi = C[mf][0][ci] + br[0][jj] + pxy.x * Axl[0][jj] + pxy.y * Ayl[0][jj];
                        float vf = C[mf][1][ci] + br[1][jj] + pxy.x * Axl[1][jj] + pxy.y * Ayl[1][jj];
                        float vg = C[mf][2][ci] + br[2][jj] + pxy.x * Axl[2][jj] + pxy.y * Ayl[2][jj];
                        float vo = C[mf][3][ci] + br[3][jj] + pxy.x * Axl[3][jj] + pxy.y * Ayl[3][jj];
                        int s = ((blk * 2 + mf) * 2 + rh) * 2 + jj;
                        float c = cst[s];
                        c = sigf(vf) * c + sigf(vi) * tanhfast(vg);
                        cst[s] = c;
                        hv[jj] = sigf(vo) * tanhfast(c);
                    }
                    uint32_t hi, lo; split2(hv[0], hv[1], hi, lo);
                    int e = row * XPITCH + j0 + 2 * tig;
                    *(uint32_t*)&Xn1[e] = hi;
                    *(uint32_t*)&Xn2[e] = lo;
                    if (!isObs) {
                        float pd0 = hv[0] * wo0[0] + hv[1] * wo0[1];
                        float pd1 = hv[0] * wo1[0] + hv[1] * wo1[1];
                        pd0 += __shfl_xor_sync(0xffffffffu, pd0, 1);
                        pd0 += __shfl_xor_sync(0xffffffffu, pd0, 2);
                        pd1 += __shfl_xor_sync(0xffffffffu, pd1, 1);
                        pd1 += __shfl_xor_sync(0xffffffffu, pd1, 2);
                        if (tig == 0)
                            *(float2*)&shRed[(w * BT + row) * 2] = make_float2(pd0, pd1);
                    }
                }
        }

        if (!isObs) {
            __syncthreads();
            if (tid < BT) {
                float d0 = shWout[256], d1 = shWout[257];
                #pragma unroll
                for (int ww = 0; ww < 16; ww++) {
                    float2 v = *(float2*)&shRed[(ww * BT + tid) * 2];
                    d0 += v.x; d1 += v.y;
                }
                int p = step - T_OBS;
                *(float2*)&out[((size_t)(gb0 + tid) * PRED + p) * 2] = make_float2(d0, d1);
                shPXY[tid] = make_float2(d0, d1);   // feed back as prev for next step
            }
        }
        __syncthreads();   // end of step: Xn + shPXY visible to all
    }
}

// ---------------- launch ----------------
extern "C" void kernel_launch(void* const* d_in, const int* in_sizes, int n_in,
                              void* d_out, int out_size)
{
    const float* obs   = (const float*)d_in[0];
    const float* nbr   = (const float*)d_in[1];
    const float* embed = (const float*)d_in[2];
    const float* W_in  = (const float*)d_in[3];
    const float* b_in  = (const float*)d_in[4];
    const float* W_sp  = (const float*)d_in[5];
    const float* b_sp  = (const float*)d_in[6];
    const float* W_ih  = (const float*)d_in[7];
    const float* W_hh  = (const float*)d_in[8];
    const float* b_ih  = (const float*)d_in[9];
    const float* b_hh  = (const float*)d_in[10];
    const float* W_out = (const float*)d_in[11];
    const float* b_out = (const float*)d_in[12];
    float* out = (float*)d_out;

    int B = in_sizes[0] / (T_OBS * 2);

    prep_kernel<<<G4 / 4, 128>>>(W_in, b_in, W_sp, b_sp, W_ih, W_hh, b_ih, b_hh, embed);
    hist_kernel<<<(B + 3) / 4, 128>>>(obs, nbr, B);

    cudaFuncSetAttribute(lstm_kernel, cudaFuncAttributeMaxDynamicSharedMemorySize, SMEM_REQ);
    lstm_kernel<<<B / BT, THREADS, SMEM_REQ>>>(W_out, b_out, out, B);
}